// round 4
// baseline (speedup 1.0000x reference)
#include <cuda_runtime.h>
#include <math_constants.h>

#define NB    148
#define TM    64
#define DF    128
#define OUTF  128
#define BATCH 16

#define XDPAD 264      // Xdup row stride in floats (128 dup-pairs + pad)
#define NPPAD 132
#define APAD  132
#define SROW  18

// Shared layout (float offsets)
#define OFF_W    0
#define OFF_XD   (OFF_W + OUTF*DF)          // 16384
#define OFF_NP   (OFF_XD + TM*XDPAD)        // 33280
#define OFF_ANC  (OFF_NP + TM*NPPAD)        // 41728
#define OFF_W2   (OFF_ANC + BATCH*APAD)     // 43840
#define OFF_S    (OFF_W2 + 128)             // 43968
#define OFF_SC   (OFF_S + TM*SROW)          // 45120
#define OFF_MB   (OFF_SC + 16)
#define OFF_LB   (OFF_MB + 16)
#define OFF_FLG  (OFF_LB + 16)
#define SMEM_FLOATS (OFF_FLG + 4)
#define SMEM_BYTES  (SMEM_FLOATS * 4)       // ~180.7 KB

typedef unsigned long long ull;

__device__ __forceinline__ ull ffma2(ull a, ull b, ull c) {
    ull d; asm("fma.rn.f32x2 %0, %1, %2, %3;" : "=l"(d) : "l"(a), "l"(b), "l"(c)); return d;
}
__device__ __forceinline__ ull fadd2(ull a, ull b) {
    ull d; asm("add.rn.f32x2 %0, %1, %2;" : "=l"(d) : "l"(a), "l"(b)); return d;
}
__device__ __forceinline__ ull fmul2(ull a, ull b) {
    ull d; asm("mul.rn.f32x2 %0, %1, %2;" : "=l"(d) : "l"(a), "l"(b)); return d;
}
__device__ __forceinline__ float2 unpk(ull v) {
    float2 r; asm("mov.b64 {%0, %1}, %2;" : "=f"(r.x), "=f"(r.y) : "l"(v)); return r;
}

// Global scratch
__device__ float g_W1t[DF * OUTF];          // [k][o] = W1[o][128+k]
__device__ float g_anchor[BATCH * OUTF];    // [b][o]
__device__ float g_pm[NB * BATCH];
__device__ float g_pl[NB * BATCH];
__device__ float g_pv[NB * BATCH * DF];
__device__ int   g_cnt = 0;

// ---------------------------------------------------------------------------
// Prep: W1 node-half transpose -> g_W1t; warp-per-dot anchor part.
// ---------------------------------------------------------------------------
__global__ __launch_bounds__(512)
void prep_kernel(const float* __restrict__ xxa, const float* __restrict__ W1) {
    int blk = blockIdx.x;
    if (blk < 8) {
        int idx = blk * 512 + threadIdx.x;          // 0..4095 float4s
        int o = idx >> 5, k4 = (idx & 31) * 4;
        float4 v = *(const float4*)&W1[o * 256 + 128 + k4];
        g_W1t[(k4 + 0) * 128 + o] = v.x;
        g_W1t[(k4 + 1) * 128 + o] = v.y;
        g_W1t[(k4 + 2) * 128 + o] = v.z;
        g_W1t[(k4 + 3) * 128 + o] = v.w;
    } else {
        int gw = (blk - 8) * 16 + (threadIdx.x >> 5);   // 0..2047 warp-dots
        int lane = threadIdx.x & 31;
        int b = gw >> 7, o = gw & 127;
        float4 xa = *(const float4*)&xxa[b * 128 + lane * 4];
        float4 wv = *(const float4*)&W1[o * 256 + lane * 4];
        float s = xa.x * wv.x;
        s = fmaf(xa.y, wv.y, s);
        s = fmaf(xa.z, wv.z, s);
        s = fmaf(xa.w, wv.w, s);
#pragma unroll
        for (int off = 16; off; off >>= 1)
            s += __shfl_xor_sync(0xffffffffu, s, off);
        if (lane == 0) g_anchor[b * 128 + o] = s;
    }
}

// ---------------------------------------------------------------------------
// Main fused persistent kernel (single launch does everything incl. finalize)
// ---------------------------------------------------------------------------
#define STORE_DUP(pf, row) {                                         \
    float4 a_, b_;                                                   \
    a_.x = pf.x; a_.y = pf.x; a_.z = pf.y; a_.w = pf.y;              \
    b_.x = pf.z; b_.y = pf.z; b_.z = pf.w; b_.w = pf.w;              \
    float* p_ = &XD[(row) * XDPAD + 8 * tc];                         \
    *(float4*)p_ = a_; *(float4*)(p_ + 4) = b_; }

__global__ __launch_bounds__(512, 1)
void main_kernel(const float* __restrict__ X,
                 const float* __restrict__ W2,
                 float* __restrict__ out,
                 int M, int nTiles) {
    extern __shared__ float sm[];
    float* Wsh  = sm + OFF_W;
    float* XD   = sm + OFF_XD;
    float* NPsh = sm + OFF_NP;
    float* anc  = sm + OFF_ANC;
    float* w2sh = sm + OFF_W2;
    float* s_sh = sm + OFF_S;
    float* scsh = sm + OFF_SC;
    float* mbp  = sm + OFF_MB;
    float* lbp  = sm + OFF_LB;

    const int tid = threadIdx.x, bx = blockIdx.x;
    const int tr = tid >> 5, tc = tid & 31;
    const int dd = tid & 127;
    const int b0 = (tid >> 7) * 4;

    // ---- Preamble: block-persistent shared state ----
    {
        const float4* src = (const float4*)g_W1t;
        float4* dst = (float4*)Wsh;
#pragma unroll
        for (int it = 0; it < 8; it++) dst[tid + it * 512] = src[tid + it * 512];
        for (int i = tid; i < BATCH * OUTF; i += 512)
            anc[(i >> 7) * APAD + (i & 127)] = g_anchor[i];
        if (tid < 128) w2sh[tid] = W2[tid];
        if (tid < 16) { mbp[tid] = -CUDART_INF_F; lbp[tid] = 0.f; }
    }

    // ---- Register prefetch of first tile ----
    float4 pf0, pf1, pf2, pf3;
    if (bx < nTiles) {
        int m0 = bx * TM;
        pf0 = *(const float4*)&X[(size_t)min(m0 + tr,      M - 1) * DF + 4 * tc];
        pf1 = *(const float4*)&X[(size_t)min(m0 + tr + 16, M - 1) * DF + 4 * tc];
        pf2 = *(const float4*)&X[(size_t)min(m0 + tr + 32, M - 1) * DF + 4 * tc];
        pf3 = *(const float4*)&X[(size_t)min(m0 + tr + 48, M - 1) * DF + 4 * tc];
    }

    ull v01 = 0ull, v23 = 0ull;

    for (int t = bx; t < nTiles; t += NB) {
        __syncthreads();                    // prior consumers of XD/s_sh done

        // ---- Stage A: regs -> duplicated smem layout ----
        STORE_DUP(pf0, tr)
        STORE_DUP(pf1, tr + 16)
        STORE_DUP(pf2, tr + 32)
        STORE_DUP(pf3, tr + 48)
        __syncthreads();

        // issue next-tile LDGs; latency hides under B/C/D
        {
            int tn = t + NB;
            if (tn < nTiles) {
                int m0n = tn * TM;
                pf0 = *(const float4*)&X[(size_t)min(m0n + tr,      M - 1) * DF + 4 * tc];
                pf1 = *(const float4*)&X[(size_t)min(m0n + tr + 16, M - 1) * DF + 4 * tc];
                pf2 = *(const float4*)&X[(size_t)min(m0n + tr + 32, M - 1) * DF + 4 * tc];
                pf3 = *(const float4*)&X[(size_t)min(m0n + tr + 48, M - 1) * DF + 4 * tc];
            }
        }

        // ---- Stage B: NP[r][o] = sum_k X[r][k]*Wt[k][o]; pure FFMA2, no movs ----
        {
            const int row0 = 4 * tr;
            const ulonglong2* xp0 = (const ulonglong2*)&XD[(row0 + 0) * XDPAD];
            const ulonglong2* xp1 = (const ulonglong2*)&XD[(row0 + 1) * XDPAD];
            const ulonglong2* xp2 = (const ulonglong2*)&XD[(row0 + 2) * XDPAD];
            const ulonglong2* xp3 = (const ulonglong2*)&XD[(row0 + 3) * XDPAD];
            const float* wp = Wsh + 4 * tc;

            ull a00 = 0, a01 = 0, a10 = 0, a11 = 0;
            ull a20 = 0, a21 = 0, a30 = 0, a31 = 0;

#pragma unroll 2
            for (int k = 0; k < DF; k += 4) {
                int kh = k >> 1;
                ulonglong2 xA = xp0[kh], xA2 = xp0[kh + 1];
                ulonglong2 xB = xp1[kh], xB2 = xp1[kh + 1];
                ulonglong2 xC = xp2[kh], xC2 = xp2[kh + 1];
                ulonglong2 xDv = xp3[kh], xD2 = xp3[kh + 1];
                ulonglong2 w0 = *(const ulonglong2*)(wp + (k + 0) * OUTF);
                ulonglong2 w1 = *(const ulonglong2*)(wp + (k + 1) * OUTF);
                ulonglong2 w2 = *(const ulonglong2*)(wp + (k + 2) * OUTF);
                ulonglong2 w3 = *(const ulonglong2*)(wp + (k + 3) * OUTF);

                a00 = ffma2(xA.x,  w0.x, a00); a01 = ffma2(xA.x,  w0.y, a01);
                a10 = ffma2(xB.x,  w0.x, a10); a11 = ffma2(xB.x,  w0.y, a11);
                a20 = ffma2(xC.x,  w0.x, a20); a21 = ffma2(xC.x,  w0.y, a21);
                a30 = ffma2(xDv.x, w0.x, a30); a31 = ffma2(xDv.x, w0.y, a31);

                a00 = ffma2(xA.y,  w1.x, a00); a01 = ffma2(xA.y,  w1.y, a01);
                a10 = ffma2(xB.y,  w1.x, a10); a11 = ffma2(xB.y,  w1.y, a11);
                a20 = ffma2(xC.y,  w1.x, a20); a21 = ffma2(xC.y,  w1.y, a21);
                a30 = ffma2(xDv.y, w1.x, a30); a31 = ffma2(xDv.y, w1.y, a31);

                a00 = ffma2(xA2.x, w2.x, a00); a01 = ffma2(xA2.x, w2.y, a01);
                a10 = ffma2(xB2.x, w2.x, a10); a11 = ffma2(xB2.x, w2.y, a11);
                a20 = ffma2(xC2.x, w2.x, a20); a21 = ffma2(xC2.x, w2.y, a21);
                a30 = ffma2(xD2.x, w2.x, a30); a31 = ffma2(xD2.x, w2.y, a31);

                a00 = ffma2(xA2.y, w3.x, a00); a01 = ffma2(xA2.y, w3.y, a01);
                a10 = ffma2(xB2.y, w3.x, a10); a11 = ffma2(xB2.y, w3.y, a11);
                a20 = ffma2(xC2.y, w3.x, a20); a21 = ffma2(xC2.y, w3.y, a21);
                a30 = ffma2(xD2.y, w3.x, a30); a31 = ffma2(xD2.y, w3.y, a31);
            }
            *(ulonglong2*)&NPsh[(row0 + 0) * NPPAD + 4 * tc] = make_ulonglong2(a00, a01);
            *(ulonglong2*)&NPsh[(row0 + 1) * NPPAD + 4 * tc] = make_ulonglong2(a10, a11);
            *(ulonglong2*)&NPsh[(row0 + 2) * NPPAD + 4 * tc] = make_ulonglong2(a20, a21);
            *(ulonglong2*)&NPsh[(row0 + 3) * NPPAD + 4 * tc] = make_ulonglong2(a30, a31);
        }
        __syncthreads();

        // ---- Stage C: scores; thread owns (b, rA, rA+32) sharing anc loads ----
        {
            const int b  = tid & 15;
            const int rA = tid >> 4;
            const int rB = rA + 32;
            const float* ab  = &anc[b * APAD];
            const float* npA = &NPsh[rA * NPPAD];
            const float* npB = &NPsh[rB * NPPAD];
            float sA0 = 0.f, sA1 = 0.f, sB0 = 0.f, sB1 = 0.f;
#pragma unroll 4
            for (int o = 0; o < OUTF; o += 4) {
                ulonglong2 av = *(const ulonglong2*)(ab + o);
                float4 w = *(const float4*)&w2sh[o];
                ulonglong2 nA = *(const ulonglong2*)(npA + o);
                ulonglong2 nB = *(const ulonglong2*)(npB + o);
                float2 fA0 = unpk(fadd2(nA.x, av.x));
                float2 fA1 = unpk(fadd2(nA.y, av.y));
                float2 fB0 = unpk(fadd2(nB.x, av.x));
                float2 fB1 = unpk(fadd2(nB.y, av.y));
                sA0 = fmaf(fmaxf(fA0.x, 0.f), w.x, sA0);
                sA1 = fmaf(fmaxf(fA0.y, 0.f), w.y, sA1);
                sA0 = fmaf(fmaxf(fA1.x, 0.f), w.z, sA0);
                sA1 = fmaf(fmaxf(fA1.y, 0.f), w.w, sA1);
                sB0 = fmaf(fmaxf(fB0.x, 0.f), w.x, sB0);
                sB1 = fmaf(fmaxf(fB0.y, 0.f), w.y, sB1);
                sB0 = fmaf(fmaxf(fB1.x, 0.f), w.z, sB0);
                sB1 = fmaf(fmaxf(fB1.y, 0.f), w.w, sB1);
            }
            const int m0 = t * TM;
            s_sh[rA * SROW + b] = (m0 + rA < M) ? (sA0 + sA1) : -CUDART_INF_F;
            s_sh[rB * SROW + b] = (m0 + rB < M) ? (sB0 + sB1) : -CUDART_INF_F;
        }
        __syncthreads();

        // ---- Stage D1: online softmax, warp per batch ----
        {
            const int b = tr;
            float s0 = s_sh[tc * SROW + b];
            float s1 = s_sh[(32 + tc) * SROW + b];
            float tmax = fmaxf(s0, s1);
#pragma unroll
            for (int off = 16; off; off >>= 1)
                tmax = fmaxf(tmax, __shfl_xor_sync(0xffffffffu, tmax, off));
            float mold = mbp[b];
            float mnew = fmaxf(mold, tmax);
            float p0 = __expf(s0 - mnew);
            float p1 = __expf(s1 - mnew);
            s_sh[tc * SROW + b] = p0;
            s_sh[(32 + tc) * SROW + b] = p1;
            float ps = p0 + p1;
#pragma unroll
            for (int off = 16; off; off >>= 1)
                ps += __shfl_xor_sync(0xffffffffu, ps, off);
            float scale = __expf(mold - mnew);
            if (tc == 0) {
                mbp[b] = mnew;
                lbp[b] = lbp[b] * scale + ps;
                scsh[b] = scale;
            }
        }
        __syncthreads();

        // ---- Stage D2: V update, (x,x) pairs straight from XD ----
        {
            ull sc01 = *(const ull*)&scsh[b0];
            ull sc23 = *(const ull*)&scsh[b0 + 2];
            v01 = fmul2(v01, sc01);
            v23 = fmul2(v23, sc23);
#pragma unroll 4
            for (int r = 0; r < TM; r++) {
                ull xd  = *(const ull*)&XD[r * XDPAD + 2 * dd];
                ull p01 = *(const ull*)&s_sh[r * SROW + b0];
                ull p23 = *(const ull*)&s_sh[r * SROW + b0 + 2];
                v01 = ffma2(xd, p01, v01);
                v23 = ffma2(xd, p23, v23);
            }
        }
    }
    __syncthreads();

    // ---- Emit partials ----
    if (tid < 16) {
        g_pm[bx * 16 + tid] = mbp[tid];
        g_pl[bx * 16 + tid] = lbp[tid];
    }
    {
        float2 e01 = unpk(v01), e23 = unpk(v23);
        int base = bx * BATCH * DF + b0 * DF + dd;
        g_pv[base]          = e01.x;
        g_pv[base + DF]     = e01.y;
        g_pv[base + 2 * DF] = e23.x;
        g_pv[base + 3 * DF] = e23.y;
    }
    __threadfence();

    // ---- Last block finalizes ----
    int* flg = (int*)&sm[OFF_FLG];
    if (tid == 0) flg[0] = (atomicAdd(&g_cnt, 1) == NB - 1) ? 1 : 0;
    __syncthreads();
    if (flg[0]) {
        float* fsh = &sm[OFF_NP];   // reuse NP region
        if (tid < 16) {
            float Mx = -CUDART_INF_F;
            for (int j = 0; j < NB; j++) Mx = fmaxf(Mx, g_pm[j * 16 + tid]);
            mbp[tid] = Mx;
        }
        __syncthreads();
        for (int i = tid; i < NB * 16; i += 512)
            fsh[i] = __expf(g_pm[i] - mbp[i & 15]);
        __syncthreads();
        if (tid < 16) {
            float L = 0.f;
            for (int j = 0; j < NB; j++) L = fmaf(g_pl[j * 16 + tid], fsh[j * 16 + tid], L);
            lbp[tid] = L;
        }
        __syncthreads();
        {
            int b = tid >> 5, d4 = (tid & 31) * 4;
            float4 V = make_float4(0.f, 0.f, 0.f, 0.f);
#pragma unroll 4
            for (int j = 0; j < NB; j++) {
                float f = fsh[j * 16 + b];
                float4 pv = *(const float4*)&g_pv[j * BATCH * DF + b * DF + d4];
                V.x = fmaf(pv.x, f, V.x);
                V.y = fmaf(pv.y, f, V.y);
                V.z = fmaf(pv.z, f, V.z);
                V.w = fmaf(pv.w, f, V.w);
            }
            float inv = 1.f / lbp[b];
            *(float4*)&out[b * DF + d4] =
                make_float4(V.x * inv, V.y * inv, V.z * inv, V.w * inv);
        }
        if (tid == 0) g_cnt = 0;
    }
}

// ---------------------------------------------------------------------------
extern "C" void kernel_launch(void* const* d_in, const int* in_sizes, int n_in,
                              void* d_out, int out_size) {
    const float* xxa = (const float*)d_in[0];   // [16,128]
    const float* X   = (const float*)d_in[1];   // [M,128]
    // d_in[2] = adj (unused)
    const float* W1  = (const float*)d_in[3];   // [128,256]
    const float* W2  = (const float*)d_in[4];   // [1,128]
    float* out = (float*)d_out;

    int M = in_sizes[1] / DF;
    int nTiles = (M + TM - 1) / TM;

    cudaFuncSetAttribute(main_kernel,
                         cudaFuncAttributeMaxDynamicSharedMemorySize, SMEM_BYTES);

    prep_kernel<<<136, 512>>>(xxa, W1);
    main_kernel<<<NB, 512, SMEM_BYTES>>>(X, W2, out, M, nTiles);
}

// round 7
// speedup vs baseline: 2.2114x; 2.2114x over previous
#include <cuda_runtime.h>
#include <cuda_bf16.h>
#include <math_constants.h>
#include <cstdint>

#define NB 148
#define TM 64
#define DF 128
#define BATCH 16
#define SROW 18

// SMEM byte offsets
#define SM_WH   0            // 32768: bf16 W hi [o][k] swizzled (128-row tile)
#define SM_WL   32768        // 32768
#define SM_XH   65536        // 16384: bf16 X hi [r][k] swizzled (64-row tile)
#define SM_XL   81920        // 16384 (= SM_XH + 16384)
#define SM_XD   98304        // 67584: fp32 X dup pairs [64][264]
#define SM_NP   165888       // 33792: fp32 NP [64][132]
#define SM_ANC  199680       // 8448
#define SM_W2   208128       // 512
#define SM_S    208640       // 4608
#define SM_SC   213248
#define SM_MB   213312
#define SM_LB   213376
#define SM_FLG  213440
#define SMEM_TOTAL 213456
#define SM_FSH  SM_NP

typedef unsigned long long ull;

__device__ __forceinline__ uint32_t smem_u32(const void* p) {
    uint32_t a;
    asm("{ .reg .u64 t; cvta.to.shared.u64 t, %1; cvt.u32.u64 %0, t; }" : "=r"(a) : "l"(p));
    return a;
}
__device__ __forceinline__ ull ffma2(ull a, ull b, ull c) {
    ull d; asm("fma.rn.f32x2 %0, %1, %2, %3;" : "=l"(d) : "l"(a), "l"(b), "l"(c)); return d;
}
__device__ __forceinline__ ull fadd2(ull a, ull b) {
    ull d; asm("add.rn.f32x2 %0, %1, %2;" : "=l"(d) : "l"(a), "l"(b)); return d;
}
__device__ __forceinline__ ull fmul2(ull a, ull b) {
    ull d; asm("mul.rn.f32x2 %0, %1, %2;" : "=l"(d) : "l"(a), "l"(b)); return d;
}
__device__ __forceinline__ float2 unpk(ull v) {
    float2 r; asm("mov.b64 {%0, %1}, %2;" : "=f"(r.x), "=f"(r.y) : "l"(v)); return r;
}
__device__ __forceinline__ uint32_t cvt_bf2(float lo, float hi) {
    uint32_t r; asm("cvt.rn.bf16x2.f32 %0, %1, %2;" : "=r"(r) : "f"(hi), "f"(lo)); return r;
}
__device__ __forceinline__ void ldsm4(uint32_t* d, uint32_t a) {
    asm volatile("ldmatrix.sync.aligned.m8n8.x4.shared.b16 {%0,%1,%2,%3}, [%4];"
        : "=r"(d[0]), "=r"(d[1]), "=r"(d[2]), "=r"(d[3]) : "r"(a));
}
__device__ __forceinline__ void mma16816(float* c, const uint32_t* a, uint32_t b0, uint32_t b1) {
    asm volatile("mma.sync.aligned.m16n8k16.row.col.f32.bf16.bf16.f32 "
        "{%0,%1,%2,%3}, {%4,%5,%6,%7}, {%8,%9}, {%0,%1,%2,%3};"
        : "+f"(c[0]), "+f"(c[1]), "+f"(c[2]), "+f"(c[3])
        : "r"(a[0]), "r"(a[1]), "r"(a[2]), "r"(a[3]), "r"(b0), "r"(b1));
}
// swizzled byte offset; AC = atoms per column-step (tile_rows/8)
__device__ __forceinline__ uint32_t swz(int row, int col, int AC) {
    uint32_t o = (uint32_t)(((row >> 3) + (col >> 6) * AC) * 1024 + (row & 7) * 128 + (col & 63) * 2);
    return o ^ ((o >> 3) & 0x70);
}

__device__ uint32_t g_Wh[8192];
__device__ uint32_t g_Wl[8192];
__device__ float g_anchor[BATCH * 128];
__device__ float g_pm[NB * BATCH];
__device__ float g_pl[NB * BATCH];
__device__ float g_pv[NB * BATCH * DF];
__device__ int g_cnt = 0;

__global__ __launch_bounds__(512)
void prep_kernel(const float* __restrict__ xxa, const float* __restrict__ W1) {
    int blk = blockIdx.x;
    if (blk < 16) {
        int idx = blk * 512 + threadIdx.x;          // 8192 col-pairs
        int o = idx >> 6, k0 = (idx & 63) * 2;
        float w0 = W1[o * 256 + 128 + k0], w1 = W1[o * 256 + 128 + k0 + 1];
        uint32_t h = cvt_bf2(w0, w1);
        float h0 = __uint_as_float(h << 16), h1 = __uint_as_float(h & 0xffff0000u);
        uint32_t sw = swz(o, k0, 16) >> 2;
        g_Wh[sw] = h;
        g_Wl[sw] = cvt_bf2(w0 - h0, w1 - h1);
    } else {
        int gw = (blk - 16) * 16 + (threadIdx.x >> 5);
        int lane = threadIdx.x & 31;
        int b = gw >> 7, o = gw & 127;
        float4 xa = *(const float4*)&xxa[b * 128 + lane * 4];
        float4 wv = *(const float4*)&W1[o * 256 + lane * 4];
        float s = xa.x * wv.x;
        s = fmaf(xa.y, wv.y, s); s = fmaf(xa.z, wv.z, s); s = fmaf(xa.w, wv.w, s);
#pragma unroll
        for (int off = 16; off; off >>= 1) s += __shfl_xor_sync(0xffffffffu, s, off);
        if (lane == 0) g_anchor[b * 128 + o] = s;
    }
}

#define STORE_DUP(pf, row) {                                          \
    float4 a_, b_;                                                    \
    a_.x = pf.x; a_.y = pf.x; a_.z = pf.y; a_.w = pf.y;               \
    b_.x = pf.z; b_.y = pf.z; b_.z = pf.w; b_.w = pf.w;               \
    float* p_ = &XD[(row) * 264 + 8 * tc];                            \
    *(float4*)p_ = a_; *(float4*)(p_ + 4) = b_; }

#define STORE_BF(pf, row) {                                           \
    uint32_t h0 = cvt_bf2(pf.x, pf.y), h1 = cvt_bf2(pf.z, pf.w);      \
    float f0 = __uint_as_float(h0 << 16), f1 = __uint_as_float(h0 & 0xffff0000u); \
    float f2 = __uint_as_float(h1 << 16), f3 = __uint_as_float(h1 & 0xffff0000u); \
    uint32_t l0 = cvt_bf2(pf.x - f0, pf.y - f1);                      \
    uint32_t l1 = cvt_bf2(pf.z - f2, pf.w - f3);                      \
    uint32_t so = swz(row, 4 * tc, 8);                                \
    *(ull*)(smem + SM_XH + so) = (ull)h0 | ((ull)h1 << 32);           \
    *(ull*)(smem + SM_XL + so) = (ull)l0 | ((ull)l1 << 32); }

__global__ __launch_bounds__(512, 1)
void main_kernel(const float* __restrict__ X, const float* __restrict__ W2,
                 float* __restrict__ out, int M, int nTiles) {
    extern __shared__ char smem[];
    const uint32_t smb = smem_u32(smem);
    float* XD   = (float*)(smem + SM_XD);
    float* NPsh = (float*)(smem + SM_NP);
    float* anc  = (float*)(smem + SM_ANC);
    float* w2sh = (float*)(smem + SM_W2);
    float* s_sh = (float*)(smem + SM_S);
    float* scsh = (float*)(smem + SM_SC);
    float* mbp  = (float*)(smem + SM_MB);
    float* lbp  = (float*)(smem + SM_LB);

    const int tid = threadIdx.x, bx = blockIdx.x;
    const int tr = tid >> 5, tc = tid & 31;
    const int dd = tid & 127, b0 = (tid >> 7) * 4;

    {   // preamble
        const float4* wh = (const float4*)g_Wh;
        const float4* wl = (const float4*)g_Wl;
        float4* dh = (float4*)(smem + SM_WH);
        float4* dl = (float4*)(smem + SM_WL);
#pragma unroll
        for (int it = 0; it < 4; it++) {
            dh[tid + it * 512] = wh[tid + it * 512];
            dl[tid + it * 512] = wl[tid + it * 512];
        }
        for (int i = tid; i < BATCH * 128; i += 512)
            anc[(i >> 7) * 132 + (i & 127)] = g_anchor[i];
        if (tid < 128) w2sh[tid] = W2[tid];
        if (tid < 16) { mbp[tid] = -CUDART_INF_F; lbp[tid] = 0.f; }
    }

    // MMA geometry: warp = (mga 0..1) x (nga 0..7); lane groups for ldmatrix
    const int wid = tr, lane = tc;
    const int mga = wid >> 3, nga = wid & 7;
    const int lgrp = lane >> 3, lrow = lane & 7;
    const int aRow0 = mga * 32 + (lgrp & 1) * 8 + lrow;
    const uint32_t aB0 = smb + SM_XH + ((uint32_t)(aRow0 >> 3) << 10) + ((uint32_t)(aRow0 & 7) << 7);
    const uint32_t cxa = ((uint32_t)((lgrp >> 1) * 16)) ^ ((uint32_t)(aRow0 & 7) << 4);
    const int bRow = nga * 16 + (lgrp >> 1) * 8 + lrow;
    const uint32_t bB = smb + SM_WH + ((uint32_t)(bRow >> 3) << 10) + ((uint32_t)(bRow & 7) << 7);
    const uint32_t cxb = ((uint32_t)((lgrp & 1) * 16)) ^ ((uint32_t)(bRow & 7) << 4);
    const int npRow0 = mga * 32 + (lane >> 2);
    const int npCol  = nga * 16 + (lane & 3) * 2;

    float4 pf0, pf1, pf2, pf3;
    {
        int m0 = bx * TM;
        pf0 = *(const float4*)&X[(size_t)min(m0 + tr,      M - 1) * DF + 4 * tc];
        pf1 = *(const float4*)&X[(size_t)min(m0 + tr + 16, M - 1) * DF + 4 * tc];
        pf2 = *(const float4*)&X[(size_t)min(m0 + tr + 32, M - 1) * DF + 4 * tc];
        pf3 = *(const float4*)&X[(size_t)min(m0 + tr + 48, M - 1) * DF + 4 * tc];
    }
    ull v01 = 0ull, v23 = 0ull;

    for (int t = bx; t < nTiles; t += NB) {
        __syncthreads();
        // A: regs -> XD fp32 dup + Xh/Xl bf16 swizzled
        STORE_DUP(pf0, tr)      STORE_BF(pf0, tr)
        STORE_DUP(pf1, tr + 16) STORE_BF(pf1, tr + 16)
        STORE_DUP(pf2, tr + 32) STORE_BF(pf2, tr + 32)
        STORE_DUP(pf3, tr + 48) STORE_BF(pf3, tr + 48)
        __syncthreads();
        {
            int tn = t + NB;
            if (tn < nTiles) {
                int m0n = tn * TM;
                pf0 = *(const float4*)&X[(size_t)min(m0n + tr,      M - 1) * DF + 4 * tc];
                pf1 = *(const float4*)&X[(size_t)min(m0n + tr + 16, M - 1) * DF + 4 * tc];
                pf2 = *(const float4*)&X[(size_t)min(m0n + tr + 32, M - 1) * DF + 4 * tc];
                pf3 = *(const float4*)&X[(size_t)min(m0n + tr + 48, M - 1) * DF + 4 * tc];
            }
        }

        // B: 96 HMMA per warp (3 split-bf16 products), acc -> NPsh
        {
            float acc[2][2][4];
#pragma unroll
            for (int mt = 0; mt < 2; mt++)
#pragma unroll
                for (int nt = 0; nt < 2; nt++)
#pragma unroll
                    for (int e = 0; e < 4; e++) acc[mt][nt][e] = 0.f;
#pragma unroll
            for (int ks = 0; ks < 8; ks++) {
                uint32_t kb = (uint32_t)((ks & 3) * 32);
                uint32_t aAddr = aB0 + (uint32_t)((ks >> 2) * 8192)  + (kb ^ cxa);
                uint32_t bAddr = bB  + (uint32_t)((ks >> 2) * 16384) + (kb ^ cxb);
                uint32_t ah0[4], ah1[4], al0[4], al1[4], bh[4], bl[4];
                ldsm4(ah0, aAddr);
                ldsm4(ah1, aAddr + 2048);
                ldsm4(al0, aAddr + 16384);
                ldsm4(al1, aAddr + 18432);
                ldsm4(bh, bAddr);
                ldsm4(bl, bAddr + 32768);
#pragma unroll
                for (int mt = 0; mt < 2; mt++) {
                    const uint32_t* ah = mt ? ah1 : ah0;
                    const uint32_t* al = mt ? al1 : al0;
#pragma unroll
                    for (int nt = 0; nt < 2; nt++) {
                        mma16816(acc[mt][nt], ah, bh[2 * nt], bh[2 * nt + 1]);
                        mma16816(acc[mt][nt], ah, bl[2 * nt], bl[2 * nt + 1]);
                        mma16816(acc[mt][nt], al, bh[2 * nt], bh[2 * nt + 1]);
                    }
                }
            }
#pragma unroll
            for (int mt = 0; mt < 2; mt++)
#pragma unroll
                for (int nt = 0; nt < 2; nt++) {
                    int r = npRow0 + mt * 16, c = npCol + nt * 8;
                    *(float2*)&NPsh[r * 132 + c]       = make_float2(acc[mt][nt][0], acc[mt][nt][1]);
                    *(float2*)&NPsh[(r + 8) * 132 + c] = make_float2(acc[mt][nt][2], acc[mt][nt][3]);
                }
        }
        __syncthreads();

        // C: scores s[b][r] from NPsh
        const int m0 = t * TM;
#pragma unroll
        for (int half = 0; half < 2; half++) {
            int item = tid + half * 512;
            int r = item >> 4, b = item & 15;
            float s;
            if (m0 + r < M) {
                float sA = 0.f, sB = 0.f;
                const float* np = &NPsh[r * 132];
                const float* ab = &anc[b * 132];
#pragma unroll 8
                for (int o = 0; o < 128; o += 4) {
                    ulonglong2 n2 = *(const ulonglong2*)&np[o];
                    ulonglong2 av = *(const ulonglong2*)&ab[o];
                    float4 w = *(const float4*)&w2sh[o];
                    float2 f01 = unpk(fadd2(n2.x, av.x));
                    float2 f23 = unpk(fadd2(n2.y, av.y));
                    sA = fmaf(fmaxf(f01.x, 0.f), w.x, sA);
                    sB = fmaf(fmaxf(f01.y, 0.f), w.y, sB);
                    sA = fmaf(fmaxf(f23.x, 0.f), w.z, sA);
                    sB = fmaf(fmaxf(f23.y, 0.f), w.w, sB);
                }
                s = sA + sB;
            } else s = -CUDART_INF_F;
            s_sh[r * SROW + b] = s;
        }
        __syncthreads();

        // D1: online softmax, warp per batch
        {
            const int b = tr;
            float s0 = s_sh[tc * SROW + b];
            float s1 = s_sh[(32 + tc) * SROW + b];
            float tmax = fmaxf(s0, s1);
#pragma unroll
            for (int off = 16; off; off >>= 1)
                tmax = fmaxf(tmax, __shfl_xor_sync(0xffffffffu, tmax, off));
            float mold = mbp[b], mnew = fmaxf(mold, tmax);
            float p0 = __expf(s0 - mnew), p1 = __expf(s1 - mnew);
            s_sh[tc * SROW + b] = p0;
            s_sh[(32 + tc) * SROW + b] = p1;
            float ps = p0 + p1;
#pragma unroll
            for (int off = 16; off; off >>= 1)
                ps += __shfl_xor_sync(0xffffffffu, ps, off);
            float scale = __expf(mold - mnew);
            if (tc == 0) { mbp[b] = mnew; lbp[b] = lbp[b] * scale + ps; scsh[b] = scale; }
        }
        __syncthreads();

        // D2: V update from XD dup pairs
        {
            ull sc01 = *(const ull*)&scsh[b0];
            ull sc23 = *(const ull*)&scsh[b0 + 2];
            v01 = fmul2(v01, sc01);
            v23 = fmul2(v23, sc23);
#pragma unroll 4
            for (int r = 0; r < TM; r++) {
                ull xd  = *(const ull*)&XD[r * 264 + 2 * dd];
                ull p01 = *(const ull*)&s_sh[r * SROW + b0];
                ull p23 = *(const ull*)&s_sh[r * SROW + b0 + 2];
                v01 = ffma2(xd, p01, v01);
                v23 = ffma2(xd, p23, v23);
            }
        }
    }
    __syncthreads();

    if (tid < 16) { g_pm[bx * 16 + tid] = mbp[tid]; g_pl[bx * 16 + tid] = lbp[tid]; }
    {
        float2 e01 = unpk(v01), e23 = unpk(v23);
        int base = bx * BATCH * DF + b0 * DF + dd;
        g_pv[base] = e01.x; g_pv[base + DF] = e01.y;
        g_pv[base + 2 * DF] = e23.x; g_pv[base + 3 * DF] = e23.y;
    }
    __threadfence();

    int* flg = (int*)(smem + SM_FLG);
    if (tid == 0) flg[0] = (atomicAdd(&g_cnt, 1) == NB - 1) ? 1 : 0;
    __syncthreads();
    if (flg[0]) {
        float* fsh = (float*)(smem + SM_FSH);
        if (tid < 16) {
            float Mx = -CUDART_INF_F;
            for (int j = 0; j < NB; j++) Mx = fmaxf(Mx, g_pm[j * 16 + tid]);
            mbp[tid] = Mx;
        }
        __syncthreads();
        for (int i = tid; i < NB * 16; i += 512)
            fsh[i] = __expf(g_pm[i] - mbp[i & 15]);
        __syncthreads();
        if (tid < 16) {
            float L = 0.f;
            for (int j = 0; j < NB; j++) L = fmaf(g_pl[j * 16 + tid], fsh[j * 16 + tid], L);
            lbp[tid] = L;
        }
        __syncthreads();
        {
            int b = tid >> 5, d4 = (tid & 31) * 4;
            float4 V = make_float4(0.f, 0.f, 0.f, 0.f);
#pragma unroll 4
            for (int j = 0; j < NB; j++) {
                float f = fsh[j * 16 + b];
                float4 pv = *(const float4*)&g_pv[j * 2048 + b * 128 + d4];
                V.x = fmaf(pv.x, f, V.x); V.y = fmaf(pv.y, f, V.y);
                V.z = fmaf(pv.z, f, V.z); V.w = fmaf(pv.w, f, V.w);
            }
            float inv = 1.f / lbp[b];
            *(float4*)&out[b * 128 + d4] =
                make_float4(V.x * inv, V.y * inv, V.z * inv, V.w * inv);
        }
        if (tid == 0) g_cnt = 0;
    }
}

extern "C" void kernel_launch(void* const* d_in, const int* in_sizes, int n_in,
                              void* d_out, int out_size) {
    const float* xxa = (const float*)d_in[0];
    const float* X   = (const float*)d_in[1];
    const float* W1  = (const float*)d_in[3];
    const float* W2  = (const float*)d_in[4];
    float* out = (float*)d_out;
    int M = in_sizes[1] / DF;
    int nTiles = (M + TM - 1) / TM;
    cudaFuncSetAttribute(main_kernel, cudaFuncAttributeMaxDynamicSharedMemorySize, SMEM_TOTAL);
    prep_kernel<<<144, 512>>>(xxa, W1);
    main_kernel<<<NB, 512, SMEM_TOTAL>>>(X, W2, out, M, nTiles);
}